// round 14
// baseline (speedup 1.0000x reference)
#include <cuda_runtime.h>
#include <cstdint>

// Fused coefficients: [ka0, kc0, ka1, kc1, bias]
__device__ float g_coef[5];

#define LAYERS 8
#define N_QUBITS 16
#define THREADS 256
#define STAGES 4
#define CHUNK_ROWS 256
#define ROW_BYTES 64
#define CHUNK_BYTES (CHUNK_ROWS * ROW_BYTES)   // 16 KB
#define GRID_BLOCKS 296                        // 2 per SM (148 SMs)

__device__ __forceinline__ uint32_t smem_u32(const void* p) {
    uint32_t a;
    asm("{ .reg .u64 t; cvta.to.shared.u64 t, %1; cvt.u32.u64 %0, t; }"
        : "=r"(a) : "l"(p));
    return a;
}

__device__ __forceinline__ void mbar_wait(uint32_t bar, uint32_t parity) {
    uint32_t done;
    asm volatile(
        "{\n\t"
        ".reg .pred p;\n\t"
        "mbarrier.try_wait.parity.acquire.cta.shared::cta.b64 p, [%1], %2;\n\t"
        "selp.b32 %0, 1, 0, p;\n\t"
        "}" : "=r"(done) : "r"(bar), "r"(parity) : "memory");
    if (!done) {
        asm volatile(
            "{\n\t"
            ".reg .pred P1;\n\t"
            "W_%=:\n\t"
            "mbarrier.try_wait.parity.acquire.cta.shared::cta.b64 P1, [%0], %1, 0x989680;\n\t"
            "@P1 bra.uni D_%=;\n\t"
            "bra.uni W_%=;\n\t"
            "D_%=:\n\t"
            "}" :: "r"(bar), "r"(parity) : "memory");
    }
}

// Thread q (q=0,1) composes the 8-layer Rot chain for qubit q into one 2x2
// complex unitary, reduces it to the (A, C) pair of the closed form
//   ez(x) = A*cos(x) - C*sin(x),  and folds in the linear head.
__global__ void vqc_precompute_kernel(const float* __restrict__ params,
                                      const float* __restrict__ head_w,
                                      const float* __restrict__ head_b) {
    int q = threadIdx.x;
    if (q >= 2) return;

    float u00r = 1.f, u00i = 0.f, u01r = 0.f, u01i = 0.f;
    float u10r = 0.f, u10i = 0.f, u11r = 1.f, u11i = 0.f;

    #pragma unroll
    for (int l = 0; l < LAYERS; l++) {
        float phi   = params[l * (N_QUBITS * 3) + q * 3 + 0];
        float theta = params[l * (N_QUBITS * 3) + q * 3 + 1];
        float omega = params[l * (N_QUBITS * 3) + q * 3 + 2];
        float ct, st, cp, sp, cm, sm;
        __sincosf(0.5f * theta, &st, &ct);
        __sincosf(-0.5f * (phi + omega), &sp, &cp);
        __sincosf(0.5f * (phi - omega), &sm, &cm);
        float m00r =  cp * ct, m00i =  sp * ct;
        float m01r = -cm * st, m01i = -sm * st;
        float m10r =  cm * st, m10i = -sm * st;
        float m11r =  cp * ct, m11i = -sp * ct;

        float n00r = m00r*u00r - m00i*u00i + m01r*u10r - m01i*u10i;
        float n00i = m00r*u00i + m00i*u00r + m01r*u10i + m01i*u10r;
        float n01r = m00r*u01r - m00i*u01i + m01r*u11r - m01i*u11i;
        float n01i = m00r*u01i + m00i*u01r + m01r*u11i + m01i*u11r;
        float n10r = m10r*u00r - m10i*u00i + m11r*u10r - m11i*u10i;
        float n10i = m10r*u00i + m10i*u00r + m11r*u10i + m11i*u10r;
        float n11r = m10r*u01r - m10i*u01i + m11r*u11r - m11i*u11i;
        float n11i = m10r*u01i + m10i*u01r + m11r*u11i + m11i*u11r;
        u00r = n00r; u00i = n00i; u01r = n01r; u01i = n01i;
        u10r = n10r; u10i = n10i; u11r = n11r; u11i = n11i;
    }

    float A = (u00r*u00r + u00i*u00i) - (u10r*u10r + u10i*u10i);
    float C = (u00i*u01r - u00r*u01i) - (u10i*u11r - u10r*u11i);

    float w = head_w[q];
    g_coef[q * 2 + 0] = w * A;
    g_coef[q * 2 + 1] = w * C;
    if (q == 0) g_coef[4] = head_b[0];
}

// Persistent deep-pipelined TMA streaming kernel.
// 296 persistent blocks (2/SM), each running a 4-stage ring of 16 KB
// cp.async.bulk chunks -> up to 128 KB of DRAM fills in flight per SM,
// far beyond the per-SM LDG miss-tracking budget (~4-5 KB) that pinned
// every LDG variant at ~3.9 TB/s. Thread 0 produces; all 256 threads
// consume one row each per chunk and arrive on the stage's empty barrier.
__global__ void __launch_bounds__(THREADS)
vqc_main_kernel(const float* __restrict__ X, float* __restrict__ out,
                int B, int nchunks) {
    extern __shared__ char buf[];              // STAGES * CHUNK_BYTES
    __shared__ alignas(8) unsigned long long full_bar[STAGES];
    __shared__ alignas(8) unsigned long long empty_bar[STAGES];

    int tid = threadIdx.x;

    if (tid == 0) {
        #pragma unroll
        for (int s = 0; s < STAGES; s++) {
            asm volatile("mbarrier.init.shared::cta.b64 [%0], 1;"
                         :: "r"(smem_u32(&full_bar[s])) : "memory");
            asm volatile("mbarrier.init.shared::cta.b64 [%0], %1;"
                         :: "r"(smem_u32(&empty_bar[s])), "r"(THREADS) : "memory");
        }
        asm volatile("fence.proxy.async.shared::cta;" ::: "memory");
    }
    __syncthreads();

    float ka0 = g_coef[0], kc0 = g_coef[1];
    float ka1 = g_coef[2], kc1 = g_coef[3];
    float bias = g_coef[4];

    for (int j = 0; ; j++) {
        int chunk = blockIdx.x + j * gridDim.x;
        if (chunk >= nchunks) break;

        int s = j & (STAGES - 1);
        uint32_t wrap = (uint32_t)(j >> 2) & 1u;   // phase flips per ring wrap
        uint32_t fbar = smem_u32(&full_bar[s]);
        uint32_t ebar = smem_u32(&empty_bar[s]);

        int base = chunk * CHUNK_ROWS;
        int rows = B - base;
        if (rows > CHUNK_ROWS) rows = CHUNK_ROWS;
        unsigned bytes = (unsigned)rows * ROW_BYTES;

        // ---- producer: wait stage empty (first pass: parity 1 succeeds on
        // a fresh barrier), then issue the bulk copy.
        if (tid == 0) {
            mbar_wait(ebar, wrap ^ 1u);
            asm volatile("mbarrier.arrive.expect_tx.shared::cta.b64 _, [%0], %1;"
                         :: "r"(fbar), "r"(bytes) : "memory");
            const char* src = (const char*)(X + (size_t)base * N_QUBITS);
            asm volatile(
                "cp.async.bulk.shared::cta.global.mbarrier::complete_tx::bytes "
                "[%0], [%1], %2, [%3];"
                :: "r"(smem_u32(buf) + s * CHUNK_BYTES), "l"(src), "r"(bytes),
                   "r"(fbar) : "memory");
        }

        // ---- consumers: wait for the chunk, compute, release the stage.
        mbar_wait(fbar, wrap);

        if (tid < rows) {
            const float* row = (const float*)(buf + s * CHUNK_BYTES
                                              + tid * ROW_BYTES);
            float x0 = row[0];
            float x1 = row[1];
            float s0, c0, s1, c1;
            __sincosf(x0, &s0, &c0);
            __sincosf(x1, &s1, &c1);
            out[base + tid] = fmaf(ka0, c0, fmaf(-kc0, s0,
                              fmaf(ka1, c1, fmaf(-kc1, s1, bias))));
        }

        asm volatile("mbarrier.arrive.shared::cta.b64 _, [%0];"
                     :: "r"(ebar) : "memory");
    }
}

extern "C" void kernel_launch(void* const* d_in, const int* in_sizes, int n_in,
                              void* d_out, int out_size) {
    const float* X      = (const float*)d_in[0];   // [B, 16]
    const float* params = (const float*)d_in[1];   // [8, 16, 3]
    const float* head_w = (const float*)d_in[2];   // [1, 2]
    const float* head_b = (const float*)d_in[3];   // [1]
    float* out = (float*)d_out;

    int B = in_sizes[0] / N_QUBITS;
    int nchunks = (B + CHUNK_ROWS - 1) / CHUNK_ROWS;

    static int smem_set = 0;
    if (!smem_set) {
        cudaFuncSetAttribute(vqc_main_kernel,
                             cudaFuncAttributeMaxDynamicSharedMemorySize,
                             STAGES * CHUNK_BYTES);
        smem_set = 1;
    }

    vqc_precompute_kernel<<<1, 32>>>(params, head_w, head_b);
    vqc_main_kernel<<<GRID_BLOCKS, THREADS, STAGES * CHUNK_BYTES>>>(
        X, out, B, nchunks);
}

// round 15
// speedup vs baseline: 1.4244x; 1.4244x over previous
#include <cuda_runtime.h>

// Fused coefficients: [ka0, kc0, ka1, kc1, bias]
__device__ float g_coef[5];

#define LAYERS 8
#define N_QUBITS 16
#define THREADS 256
#define RPT 4          // rows per thread, branch-free

// Thread q (q=0,1) composes the 8-layer Rot chain for qubit q into one 2x2
// complex unitary, reduces it to the (A, C) pair of the closed form
//   ez(x) = A*cos(x) - C*sin(x),  and folds in the linear head.
__global__ void vqc_precompute_kernel(const float* __restrict__ params,
                                      const float* __restrict__ head_w,
                                      const float* __restrict__ head_b) {
    int q = threadIdx.x;
    if (q >= 2) return;

    float u00r = 1.f, u00i = 0.f, u01r = 0.f, u01i = 0.f;
    float u10r = 0.f, u10i = 0.f, u11r = 1.f, u11i = 0.f;

    #pragma unroll
    for (int l = 0; l < LAYERS; l++) {
        float phi   = params[l * (N_QUBITS * 3) + q * 3 + 0];
        float theta = params[l * (N_QUBITS * 3) + q * 3 + 1];
        float omega = params[l * (N_QUBITS * 3) + q * 3 + 2];
        float ct, st, cp, sp, cm, sm;
        __sincosf(0.5f * theta, &st, &ct);
        __sincosf(-0.5f * (phi + omega), &sp, &cp);
        __sincosf(0.5f * (phi - omega), &sm, &cm);
        // Rot(phi,theta,omega) = RZ(omega) RY(theta) RZ(phi)
        float m00r =  cp * ct, m00i =  sp * ct;
        float m01r = -cm * st, m01i = -sm * st;
        float m10r =  cm * st, m10i = -sm * st;
        float m11r =  cp * ct, m11i = -sp * ct;

        float n00r = m00r*u00r - m00i*u00i + m01r*u10r - m01i*u10i;
        float n00i = m00r*u00i + m00i*u00r + m01r*u10i + m01i*u10r;
        float n01r = m00r*u01r - m00i*u01i + m01r*u11r - m01i*u11i;
        float n01i = m00r*u01i + m00i*u01r + m01r*u11i + m01i*u11r;
        float n10r = m10r*u00r - m10i*u00i + m11r*u10r - m11i*u10i;
        float n10i = m10r*u00i + m10i*u00r + m11r*u10i + m11i*u10r;
        float n11r = m10r*u01r - m10i*u01i + m11r*u11r - m11i*u11i;
        float n11i = m10r*u01i + m10i*u01r + m11r*u11i + m11i*u11r;
        u00r = n00r; u00i = n00i; u01r = n01r; u01i = n01i;
        u10r = n10r; u10i = n10i; u11r = n11r; u11i = n11i;
    }

    float A = (u00r*u00r + u00i*u00i) - (u10r*u10r + u10i*u10i);
    float C = (u00i*u01r - u00r*u01i) - (u10i*u11r - u10r*u11i);

    float w = head_w[q];
    g_coef[q * 2 + 0] = w * A;
    g_coef[q * 2 + 1] = w * C;
    if (q == 0) g_coef[4] = head_b[0];
}

// Branch-free MLP-4 streaming kernel. B is covered EXACTLY by
// grid*THREADS*RPT, so there are no bounds checks: the 4 row loads are
// straight-line back-to-back in SASS (MLP_p1 = 4), quadrupling the
// requested bytes in flight vs the 1-load-per-thread variant. Previous
// MLP attempts guarded every load with `if (b < B)`, which split them
// into separate branch regions and defeated front-batching.
__global__ void __launch_bounds__(THREADS)
vqc_main_kernel(const float* __restrict__ X, float* __restrict__ out) {
    int tid = blockIdx.x * blockDim.x + threadIdx.x;
    int nthreads = gridDim.x * blockDim.x;

    float x0[RPT], x1[RPT];

    #pragma unroll
    for (int i = 0; i < RPT; i++) {
        const float* p = X + (size_t)(tid + i * nthreads) * N_QUBITS;
        asm volatile("ld.global.cg.v2.f32 {%0, %1}, [%2];"
                     : "=f"(x0[i]), "=f"(x1[i]) : "l"(p));
    }

    float ka0 = g_coef[0], kc0 = g_coef[1];
    float ka1 = g_coef[2], kc1 = g_coef[3];
    float bias = g_coef[4];

    #pragma unroll
    for (int i = 0; i < RPT; i++) {
        float s0, c0, s1, c1;
        __sincosf(x0[i], &s0, &c0);
        __sincosf(x1[i], &s1, &c1);
        out[tid + i * nthreads] = fmaf(ka0, c0, fmaf(-kc0, s0,
                                  fmaf(ka1, c1, fmaf(-kc1, s1, bias))));
    }
}

// Fallback with bounds checks, used only if B is not exactly divisible.
__global__ void __launch_bounds__(THREADS)
vqc_main_kernel_guarded(const float* __restrict__ X, float* __restrict__ out,
                        int B) {
    int b = blockIdx.x * blockDim.x + threadIdx.x;
    if (b >= B) return;
    const float* p = X + (size_t)b * N_QUBITS;
    float x0, x1;
    asm volatile("ld.global.cg.v2.f32 {%0, %1}, [%2];"
                 : "=f"(x0), "=f"(x1) : "l"(p));
    float s0, c0, s1, c1;
    __sincosf(x0, &s0, &c0);
    __sincosf(x1, &s1, &c1);
    out[b] = fmaf(g_coef[0], c0, fmaf(-g_coef[1], s0,
             fmaf(g_coef[2], c1, fmaf(-g_coef[3], s1, g_coef[4]))));
}

extern "C" void kernel_launch(void* const* d_in, const int* in_sizes, int n_in,
                              void* d_out, int out_size) {
    const float* X      = (const float*)d_in[0];   // [B, 16]
    const float* params = (const float*)d_in[1];   // [8, 16, 3]
    const float* head_w = (const float*)d_in[2];   // [1, 2]
    const float* head_b = (const float*)d_in[3];   // [1]
    float* out = (float*)d_out;

    int B = in_sizes[0] / N_QUBITS;

    vqc_precompute_kernel<<<1, 32>>>(params, head_w, head_b);

    if (B % (THREADS * RPT) == 0) {
        int blocks = B / (THREADS * RPT);   // 512 for B=524288
        vqc_main_kernel<<<blocks, THREADS>>>(X, out);
    } else {
        vqc_main_kernel_guarded<<<(B + THREADS - 1) / THREADS, THREADS>>>(
            X, out, B);
    }
}